// round 5
// baseline (speedup 1.0000x reference)
#include <cuda_runtime.h>

#define T_STEPS 2048
#define BATCH   256
#define HDIM    200
#define IN_DIM  27
#define NCLS    2

#define NB_TILES 16
#define NH_TILES 8
#define GRID_CTAS (NB_TILES * NH_TILES)   // 128 persistent CTAs, 1/SM
#define TB 16     // batches per CTA
#define TH 25     // hidden units per CTA
#define ROWS 100  // 4 gates * TH weight rows
#define ROWS_PAD 128
#define NTHREADS 256

// SMEM strides (floats), padded for conflict-free LDS.64
#define WHH_S 210
#define WIH_S 30
#define HS_S  204
#define XS_S  30
#define GS_S  17

struct SmemLayout {
    float whh[ROWS_PAD][WHH_S];    // 107520 B
    float wih[ROWS_PAD][WIH_S];    //  15360 B
    float hs[TB][HS_S];            //  13056 B
    float xs[TB][XS_S];            //   1920 B
    float bias[ROWS_PAD];          //    512 B
    float gates[ROWS_PAD][GS_S];   //   8704 B
    float c[TB][TH + 1];           //   1664 B
};
// total 148736 B -> exactly 1 CTA/SM; 128 <= 148 SMs so all co-resident.

__device__ float g_h[2][BATCH][HDIM];
__device__ unsigned int g_count;
__device__ unsigned int g_epoch;

typedef unsigned long long u64;

__device__ __forceinline__ u64 ld2(const float* p) {
    return *reinterpret_cast<const u64*>(p);
}
__device__ __forceinline__ void ffma2(u64& d, u64 a, u64 b) {
    asm("fma.rn.f32x2 %0, %1, %2, %3;" : "=l"(d) : "l"(a), "l"(b), "l"(d));
}
__device__ __forceinline__ float f2sum(u64 v) {
    return __uint_as_float((unsigned)v) + __uint_as_float((unsigned)(v >> 32));
}
__device__ __forceinline__ float sigf(float x) {
    return 1.0f / (1.0f + expf(-x));
}

// Sense-reversing grid barrier. Replay-safe: epoch compare is equality-based
// (wrap-safe), count self-resets each barrier.
__device__ __forceinline__ void grid_barrier() {
    __threadfence();       // every thread's prior writes visible before arrive
    __syncthreads();
    if (threadIdx.x == 0) {
        unsigned my = *(volatile unsigned*)&g_epoch;  // read BEFORE arriving
        unsigned old = atomicAdd(&g_count, 1u);
        if (old == GRID_CTAS - 1) {
            atomicExch(&g_count, 0u);
            __threadfence();
            atomicAdd(&g_epoch, 1u);
        } else {
            while (*(volatile unsigned*)&g_epoch == my) { __nanosleep(32); }
        }
        __threadfence();
    }
    __syncthreads();
}

__global__ void __launch_bounds__(NTHREADS, 1)
lstm_persistent(const float* __restrict__ x,      // [B][T][27]
                const float* __restrict__ W_ih,   // [800][27]
                const float* __restrict__ W_hh,   // [800][200]
                const float* __restrict__ b_ih,   // [800]
                const float* __restrict__ b_hh,   // [800]
                const float* __restrict__ fc_w,   // [2][200]
                const float* __restrict__ fc_b,   // [2]
                float* __restrict__ out, int out_size)
{
    extern __shared__ float smem_f[];
    SmemLayout& s = *reinterpret_cast<SmemLayout*>(smem_f);

    const int tid = threadIdx.x;
    const int bt  = blockIdx.x >> 3;   // 0..15
    const int ht  = blockIdx.x & 7;    // 0..7
    const int b0  = bt * TB;
    const int hd0 = ht * TH;

    // ---- one-time staging of weight slices (row r = gate*25 + hl) ----
    for (int i = tid; i < ROWS_PAD * HDIM; i += NTHREADS) {
        int r = i / HDIM, k = i - r * HDIM;
        float v = 0.0f;
        if (r < ROWS) {
            int gate = r / TH, hl = r - gate * TH;
            v = W_hh[(gate * HDIM + hd0 + hl) * HDIM + k];
        }
        s.whh[r][k] = v;
    }
    for (int i = tid; i < ROWS_PAD * 28; i += NTHREADS) {
        int r = i / 28, k = i - r * 28;
        float v = 0.0f;
        if (r < ROWS && k < IN_DIM) {
            int gate = r / TH, hl = r - gate * TH;
            v = W_ih[(gate * HDIM + hd0 + hl) * IN_DIM + k];
        }
        s.wih[r][k] = v;
    }
    if (tid < ROWS_PAD) {
        float v = 0.0f;
        if (tid < ROWS) {
            int gate = tid / TH, hl = tid - gate * TH;
            int gr = gate * HDIM + hd0 + hl;
            v = b_ih[gr] + b_hh[gr];
        }
        s.bias[tid] = v;
    }
    // TB*TH = 400 > 256 threads -> stride loop, not a guard.
    for (int i = tid; i < TB * TH; i += NTHREADS) {
        s.c[i / TH][i % TH] = 0.0f;
    }

    // thread tile: rows r0,r0+1  x  batches bb, bb+4, bb+8, bb+12
    const int jb = tid >> 2;
    const int bb = tid & 3;
    const int r0 = 2 * jb;

    for (int t = 0; t < T_STEPS; ++t) {
        // stage x (pad 27 -> 28 with zero)
        for (int i = tid; i < TB * 28; i += NTHREADS) {
            int bl = i / 28, k = i - bl * 28;
            s.xs[bl][k] = (k < IN_DIM)
                ? x[((size_t)(b0 + bl) * T_STEPS + t) * IN_DIM + k] : 0.0f;
        }
        // stage h_prev (written to g_h[t&1] by previous step)
        if (t > 0) {
            const float4* hsrc = reinterpret_cast<const float4*>(&g_h[t & 1][b0][0]);
            for (int i = tid; i < TB * (HDIM / 4); i += NTHREADS) {
                int bl = i / 50, kq = i - bl * 50;
                float4 v = hsrc[i];
                *reinterpret_cast<float4*>(&s.hs[bl][kq * 4]) = v;
            }
        }
        __syncthreads();

        u64 a00 = 0, a01 = 0, a10 = 0, a11 = 0, a20 = 0, a21 = 0, a30 = 0, a31 = 0;

        #pragma unroll
        for (int kp = 0; kp < 14; ++kp) {           // input projection (28 cols)
            u64 w0 = ld2(&s.wih[r0][2 * kp]);
            u64 w1 = ld2(&s.wih[r0 + 1][2 * kp]);
            u64 v0 = ld2(&s.xs[bb][2 * kp]);
            u64 v1 = ld2(&s.xs[bb + 4][2 * kp]);
            u64 v2 = ld2(&s.xs[bb + 8][2 * kp]);
            u64 v3 = ld2(&s.xs[bb + 12][2 * kp]);
            ffma2(a00, v0, w0); ffma2(a01, v0, w1);
            ffma2(a10, v1, w0); ffma2(a11, v1, w1);
            ffma2(a20, v2, w0); ffma2(a21, v2, w1);
            ffma2(a30, v3, w0); ffma2(a31, v3, w1);
        }
        if (t > 0) {                                // recurrent part, K=200
            #pragma unroll 5
            for (int kp = 0; kp < HDIM / 2; ++kp) {
                u64 w0 = ld2(&s.whh[r0][2 * kp]);
                u64 w1 = ld2(&s.whh[r0 + 1][2 * kp]);
                u64 v0 = ld2(&s.hs[bb][2 * kp]);
                u64 v1 = ld2(&s.hs[bb + 4][2 * kp]);
                u64 v2 = ld2(&s.hs[bb + 8][2 * kp]);
                u64 v3 = ld2(&s.hs[bb + 12][2 * kp]);
                ffma2(a00, v0, w0); ffma2(a01, v0, w1);
                ffma2(a10, v1, w0); ffma2(a11, v1, w1);
                ffma2(a20, v2, w0); ffma2(a21, v2, w1);
                ffma2(a30, v3, w0); ffma2(a31, v3, w1);
            }
        }

        // scatter gate pre-activations (bias folded in)
        {
            float bsum0 = s.bias[r0], bsum1 = s.bias[r0 + 1];
            s.gates[r0][bb]          = f2sum(a00) + bsum0;
            s.gates[r0 + 1][bb]      = f2sum(a01) + bsum1;
            s.gates[r0][bb + 4]      = f2sum(a10) + bsum0;
            s.gates[r0 + 1][bb + 4]  = f2sum(a11) + bsum1;
            s.gates[r0][bb + 8]      = f2sum(a20) + bsum0;
            s.gates[r0 + 1][bb + 8]  = f2sum(a21) + bsum1;
            s.gates[r0][bb + 12]     = f2sum(a30) + bsum0;
            s.gates[r0 + 1][bb + 12] = f2sum(a31) + bsum1;
        }
        __syncthreads();

        // cell update: 400 (b, hl) items over 256 threads (stride loop).
        for (int i = tid; i < TB * TH; i += NTHREADS) {
            int b = i / TH, hl = i - b * TH;
            float gi = sigf(s.gates[hl][b]);
            float gf = sigf(s.gates[TH + hl][b]);
            float gg = tanhf(s.gates[2 * TH + hl][b]);
            float go = sigf(s.gates[3 * TH + hl][b]);
            float c = gf * s.c[b][hl] + gi * gg;
            s.c[b][hl] = c;
            g_h[(t + 1) & 1][b0 + b][hd0 + hl] = go * tanhf(c);
        }
        grid_barrier();
    }

    // final h is in g_h[0] (2048 is even). Outputs: [out(512) | h(51200) | c(51200)]
    if (ht == 0 && tid < TB * NCLS && out_size >= NCLS * BATCH) {
        int b = b0 + tid / NCLS, cls = tid & 1;
        float acc = fc_b[cls];
        for (int k = 0; k < HDIM; ++k)
            acc += g_h[0][b][k] * fc_w[cls * HDIM + k];
        out[b * NCLS + cls] = sigf(acc);
    }
    if (ht == 0 && out_size >= NCLS * BATCH + BATCH * HDIM) {
        for (int i = tid; i < TB * HDIM; i += NTHREADS) {
            int bl = i / HDIM, k = i - bl * HDIM;
            out[NCLS * BATCH + (size_t)(b0 + bl) * HDIM + k] = g_h[0][b0 + bl][k];
        }
    }
    if (out_size >= NCLS * BATCH + 2 * BATCH * HDIM) {
        for (int i = tid; i < TB * TH; i += NTHREADS) {
            int b = i / TH, hl = i - b * TH;
            out[NCLS * BATCH + BATCH * HDIM + (size_t)(b0 + b) * HDIM + hd0 + hl]
                = s.c[b][hl];
        }
    }
}

extern "C" void kernel_launch(void* const* d_in, const int* in_sizes, int n_in,
                              void* d_out, int out_size) {
    const float* x     = (const float*)d_in[0];
    // d_in[1] = X_lengths (unused by reference), d_in[2]=h0, d_in[3]=c0 (zeros, ignored)
    const float* W_ih  = (const float*)d_in[4];
    const float* W_hh  = (const float*)d_in[5];
    const float* b_ih  = (const float*)d_in[6];
    const float* b_hh  = (const float*)d_in[7];
    const float* fc_w  = (const float*)d_in[8];
    const float* fc_b  = (const float*)d_in[9];

    int smem = (int)sizeof(SmemLayout);
    cudaFuncSetAttribute(lstm_persistent,
                         cudaFuncAttributeMaxDynamicSharedMemorySize, smem);
    lstm_persistent<<<GRID_CTAS, NTHREADS, smem>>>(
        x, W_ih, W_hh, b_ih, b_hh, fc_w, fc_b, (float*)d_out, out_size);
}